// round 1
// baseline (speedup 1.0000x reference)
#include <cuda_runtime.h>

// Patch2Im: fold [B,C,7,7,85,85] -> [B,C,259,259], normalize by coverage
// count, crop 3 on each side -> [B,C,253,253].
// Gather formulation: each output pixel sums its <=9 covering patch entries.

#define BATCH 4
#define CH 64
#define KP 7
#define STR 3
#define NH 85
#define NW 85
#define OH 253
#define OW 253
#define PAD 3
#define PS (NH * NW)          // 7225, stride of one (i,j) plane
#define TOTAL (BATCH * CH * OH * OW)

__global__ void __launch_bounds__(256)
patch2im_kernel(const float* __restrict__ xp, float* __restrict__ out)
{
    int idx = blockIdx.x * 256 + threadIdx.x;
    if (idx >= TOTAL) return;

    int w  = idx % OW;
    int t  = idx / OW;
    int h  = t % OH;
    int bc = t / OH;              // 0..255  (b*C + c)

    int hp = h + PAD;             // uncropped coords, 3..255
    int wp = w + PAD;

    // Valid (i, ph) pairs: i = hp mod 3 + {0,3,6}, ph = (hp - i)/3 in [0,85)
    int rowoff[3];
    int nh = 0;
    int rh = hp % 3;
#pragma unroll
    for (int m = 0; m < 3; ++m) {
        int i = rh + 3 * m;
        int ph = (hp - i) / 3;    // exact: hp - i divisible by 3
        if (i < KP && ph >= 0 && ph < NH)
            rowoff[nh++] = i * KP * PS + ph * NW;
    }

    int coloff[3];
    int nw = 0;
    int rw = wp % 3;
#pragma unroll
    for (int m = 0; m < 3; ++m) {
        int j = rw + 3 * m;
        int pw = (wp - j) / 3;
        if (j < KP && pw >= 0 && pw < NW)
            coloff[nw++] = j * PS + pw;
    }

    const float* base = xp + (size_t)bc * (KP * KP * PS);

    float sum = 0.0f;
#pragma unroll 3
    for (int a = 0; a < nh; ++a) {
        int ro = rowoff[a];
#pragma unroll 3
        for (int b = 0; b < nw; ++b) {
            sum += __ldg(base + ro + coloff[b]);
        }
    }

    int cnt = nh * nw;            // 1..9
    out[idx] = __fdividef(sum, (float)cnt);
}

extern "C" void kernel_launch(void* const* d_in, const int* in_sizes, int n_in,
                              void* d_out, int out_size)
{
    const float* xp = (const float*)d_in[0];
    float* out = (float*)d_out;
    int blocks = (TOTAL + 255) / 256;   // 64009 exactly
    patch2im_kernel<<<blocks, 256>>>(xp, out);
}

// round 2
// speedup vs baseline: 3.9911x; 3.9911x over previous
#include <cuda_runtime.h>

// Patch2Im gather: out[bc,h,w] = mean over <=9 covering patch entries of
// x_patch[bc, i, j, ph, pw] where h+3 = i + 3*ph, w+3 = j + 3*pw.
// Fully branchless: all 9 loads always issued (offsets clamped in-bounds),
// validity folded into {0,1} fp weights.

#define BATCH 4
#define CH 64
#define KP 7
#define NH 85
#define NW 85
#define OH 253
#define OW 253
#define PAD 3
#define PS (NH * NW)          // 7225

__global__ void __launch_bounds__(256)
patch2im_kernel(const float* __restrict__ xp, float* __restrict__ out)
{
    int w = threadIdx.x;
    if (w >= OW) return;                 // lanes 253..255 idle
    int h  = blockIdx.x;                 // 0..252
    int bc = blockIdx.y;                 // 0..255

    int hp = h + PAD;                    // 3..255
    int wp = w + PAD;

    int rh = hp % 3, qh = hp / 3;
    int rw = wp % 3, qw = wp / 3;

    float wr[3], wc[3];
    int   roff[3], coff[3];
#pragma unroll
    for (int m = 0; m < 3; ++m) {
        int i  = rh + 3 * m;             // candidate kernel row
        int ph = qh - m;                 // its patch row
        bool vr = (i < KP) && (ph >= 0) && (ph < NH);
        wr[m]   = vr ? 1.0f : 0.0f;
        roff[m] = vr ? (i * KP * PS + ph * NW) : 0;

        int j  = rw + 3 * m;             // candidate kernel col
        int pw = qw - m;                 // its patch col
        bool vcl = (j < KP) && (pw >= 0) && (pw < NW);
        wc[m]   = vcl ? 1.0f : 0.0f;
        coff[m] = vcl ? (j * PS + pw) : 0;
    }

    const float* base = xp + (size_t)bc * (KP * KP * PS);

    float sum = 0.0f;
#pragma unroll
    for (int a = 0; a < 3; ++a) {
        float rs = 0.0f;
#pragma unroll
        for (int b = 0; b < 3; ++b)
            rs += wc[b] * __ldg(base + roff[a] + coff[b]);
        sum += wr[a] * rs;
    }

    float cnt = (wr[0] + wr[1] + wr[2]) * (wc[0] + wc[1] + wc[2]);
    out[((size_t)bc * OH + h) * OW + w] = __fdividef(sum, cnt);
}

extern "C" void kernel_launch(void* const* d_in, const int* in_sizes, int n_in,
                              void* d_out, int out_size)
{
    const float* xp = (const float*)d_in[0];
    float* out = (float*)d_out;
    dim3 grid(OH, BATCH * CH);           // (253, 256)
    patch2im_kernel<<<grid, 256>>>(xp, out);
}